// round 8
// baseline (speedup 1.0000x reference)
#include <cuda_runtime.h>
#include <cstdint>

#define BB   128
#define TT   500
#define NIN  700
#define NH   200
#define NOUT 20
#define NROWS (BB*TT)          // 64000
#define CAP  256               // max active inputs per row (x4-padded with 700)

// -------- scratch (static __device__ allocations: allowed) -----------------
__device__ unsigned short g_idx[(size_t)NROWS * CAP];
__device__ int            g_cnt[NROWS];
__device__ float          g_ff[(size_t)NROWS * NH];     // cur1_ff = x@W1^T + b1

// ===========================================================================
// P0: compact active input indices per (b,t) row; pad list to x4 with 700.
// DRAM-bound (~35us floor).
// ===========================================================================
__global__ __launch_bounds__(256) void k_compact(const float* __restrict__ x)
{
    int wid  = threadIdx.x >> 5, lane = threadIdx.x & 31;
    int row  = blockIdx.x * 8 + wid;
    if (row >= NROWS) return;
    const float* xr = x + (size_t)row * NIN;
    unsigned short* out = g_idx + (size_t)row * CAP;
    unsigned lt = (1u << lane) - 1u;
    int cnt = 0;
#pragma unroll
    for (int c = 0; c < (NIN + 31) / 32; c++) {
        int i = c * 32 + lane;
        float v = (i < NIN) ? xr[i] : 0.f;
        bool a = v > 0.5f;
        unsigned m = __ballot_sync(0xffffffffu, a);
        if (a) {
            int pos = cnt + __popc(m & lt);
            if (pos < CAP) out[pos] = (unsigned short)i;
        }
        cnt += __popc(m);
    }
    if (lane == 0) {
        int c = (cnt < CAP) ? cnt : CAP;
        g_cnt[row] = c;
        int cp = c;
        while ((cp & 3) && cp < CAP) out[cp++] = 700;   // pad -> zero row
    }
}

// ===========================================================================
// P1: cur1_ff (unchanged from R7: 293us measured).
// ===========================================================================
#define P1_HC     50
#define P1_STRIDE 52
#define P1_WSLOT  64
#define OFF_BUF   (701 * P1_STRIDE)
#define P1_SMEM   ((OFF_BUF + 16 * P1_WSLOT * 2) * 4)
#define P1_GROUPS 128
#define P1_RPC    (NROWS / P1_GROUPS)

__global__ __launch_bounds__(512) void k_ff(const float* __restrict__ W1,
                                            const float* __restrict__ b1)
{
    extern __shared__ float s[];
    int tid = threadIdx.x, wid = tid >> 5, lane = tid & 31;
    int h0 = blockIdx.x * P1_HC;

    for (int i = tid; i < P1_HC * NIN; i += 512) {
        int hh = i / NIN, n = i - hh * NIN;
        s[n * P1_STRIDE + hh] = W1[(h0 + hh) * NIN + n];
    }
    for (int i = tid; i < P1_STRIDE; i += 512) s[700 * P1_STRIDE + i] = 0.f;
    __syncthreads();

    uint2* swbuf = (uint2*)(s + OFF_BUF) + wid * P1_WSLOT;
    const uint2* sbuf2 = (const uint2*)swbuf;

    int hh2 = 2 * lane;
    bool act = (lane < 25);
    float bb0 = 0.f, bb1 = 0.f;
    if (act) { bb0 = b1[h0 + hh2]; bb1 = b1[h0 + hh2 + 1]; }

    int base = blockIdx.y * P1_RPC;
    int lim  = base + P1_RPC; if (lim > NROWS) lim = NROWS;

    int row = base + wid;
    if (row >= lim) return;

    int  cnt_c = g_cnt[row];
    uint2 rA   = ((const uint2*)(g_idx + (size_t)row * CAP))[lane];

    while (row < lim) {
        int rn = row + 16;
        int  cnt_n = 0;
        uint2 nA = make_uint2(0u, 0u);
        if (rn < lim) {
            cnt_n = g_cnt[rn];
            nA = ((const uint2*)(g_idx + (size_t)rn * CAP))[lane];
        }

        swbuf[lane] = rA;
        if (cnt_c > 128)
            swbuf[32 + lane] = ((const uint2*)(g_idx + (size_t)row * CAP))[32 + lane];
        __syncwarp();

        float c0a = 0.f, c1a = 0.f, c0b = 0.f, c1b = 0.f;
        int it = (cnt_c + 3) >> 2;
#pragma unroll 2
        for (int k = 0; k < it; k++) {
            uint2 u = sbuf2[k];
            int j0 = u.x & 0xffff, j1 = u.x >> 16;
            int j2 = u.y & 0xffff, j3 = u.y >> 16;
            if (act) {
                float2 v0 = *(const float2*)&s[j0 * P1_STRIDE + hh2];
                float2 v1 = *(const float2*)&s[j1 * P1_STRIDE + hh2];
                float2 v2 = *(const float2*)&s[j2 * P1_STRIDE + hh2];
                float2 v3 = *(const float2*)&s[j3 * P1_STRIDE + hh2];
                c0a += v0.x + v1.x;  c0b += v2.x + v3.x;
                c1a += v0.y + v1.y;  c1b += v2.y + v3.y;
            }
        }
        if (act) {
            float2 o; o.x = (c0a + c0b) + bb0; o.y = (c1a + c1b) + bb1;
            *(float2*)&g_ff[(size_t)row * NH + h0 + hh2] = o;
        }
        __syncwarp();

        row = rn; cnt_c = cnt_n; rA = nA;
    }
}

// ===========================================================================
// P2 (REWRITTEN): warp-per-batch recurrent scan. 128 CTAs x 32 threads.
// Lane owns h = [4*lane, 4*lane+4) (slot A) and h = [128+4*lane, +4) (slot B,
// lane<18). Wfb^T in smem as float4 slots (row stride 200 floats, row 200=0).
// Spike list: 8 warp ballots -> ushort list (x4-padded with 200). Gather:
// uniform LDS.64 of 4 indices, LDS.128 per slot, packed add.rn.f32x2.
// Layer-2 folded into the gather with one-step deferral (+ epilogue).
// NO __syncthreads anywhere.
// ===========================================================================
#define S_W2    (201 * NH)                       // float offset of W2^T
#define S_LIST  (S_W2 + 201 * NOUT)              // float offset of list
#define P2_SMEM ((S_LIST + 128) * 4)             // list: 256 ushorts = 128 floats

#define ADD2(acc, v) asm("add.rn.f32x2 %0, %0, %1;" : "+l"(acc) : "l"(v))

__global__ __launch_bounds__(32) void k_snn(
    const float* __restrict__ Wfb,  const float* __restrict__ bfb,
    const float* __restrict__ W2,   const float* __restrict__ b2,
    const float* __restrict__ alpha1, const float* __restrict__ beta1,
    const float* __restrict__ thr1,
    const float* __restrict__ alpha2, const float* __restrict__ beta2,
    const float* __restrict__ thr2,
    float* __restrict__ out)
{
    extern __shared__ float sm[];
    float* sWfb = sm;                            // [201][200], row 200 = zeros
    float* sW2  = sm + S_W2;                     // [201][20],  row 200 = zeros
    unsigned short* slist = (unsigned short*)(sm + S_LIST);   // 256 ushorts

    int lane = threadIdx.x;
    int b = blockIdx.x;
    unsigned lt = (1u << lane) - 1u;
    bool hasB = lane < 18;
    bool has2 = lane < 20;

    // ---- load transposed weights (one-time) ----
    for (int i = lane; i < NH * NH; i += 32) {
        int h = i / NH, j = i - h * NH;
        sWfb[j * NH + h] = Wfb[i];
    }
    for (int i = lane; i < NH; i += 32) sWfb[200 * NH + i] = 0.f;
    for (int i = lane; i < NOUT * NH; i += 32) {
        int o = i / NH, j = i - o * NH;
        sW2[j * NOUT + o] = W2[i];
    }
    if (has2) sW2[200 * NOUT + lane] = 0.f;
    __syncwarp();

    // ---- per-lane parameters ----
    const float4 f4z = make_float4(0.f, 0.f, 0.f, 0.f);
    int hA = 4 * lane, hB = 128 + 4 * lane;
    float4 aA = *(const float4*)&alpha1[hA];
    float4 bA = *(const float4*)&beta1[hA];
    float4 tA = *(const float4*)&thr1[hA];
    float4 fA = *(const float4*)&bfb[hA];
    float4 aB = f4z, bB = f4z, tB = make_float4(1,1,1,1), fB = f4z;
    if (hasB) {
        aB = *(const float4*)&alpha1[hB];
        bB = *(const float4*)&beta1[hB];
        tB = *(const float4*)&thr1[hB];
        fB = *(const float4*)&bfb[hB];
    }
    float a2 = 0.f, b2v = 0.f, th2 = 1.f, bb2 = 0.f;
    if (has2) { a2 = alpha2[lane]; b2v = beta2[lane]; th2 = thr2[lane]; bb2 = b2[lane]; }

    float4 synA = f4z, memA = f4z, synB = f4z, memB = f4z;
    float syn2 = 0.f, mem2 = 0.f, rmax = __int_as_float(0xff800000u);

    const float* ffbase = g_ff + (size_t)b * TT * NH;
    float4 ffA = *(const float4*)&ffbase[hA];
    float4 ffB = hasB ? *(const float4*)&ffbase[hB] : f4z;

    const ulonglong2* wf = (const ulonglong2*)sWfb;   // [j*50 + slot]
    int cnt = 0;

    union { unsigned long long u; float2 f; } cvt;

    for (int t = 0; t < TT; t++) {
        // prefetch next step's feedforward current
        float4 nfA = f4z, nfB = f4z;
        if (t + 1 < TT) {
            nfA = *(const float4*)&ffbase[(t + 1) * NH + hA];
            if (hasB) nfB = *(const float4*)&ffbase[(t + 1) * NH + hB];
        }

        // ---- gather over list (spikes of step t-1): layer-1 + layer-2 ----
        unsigned long long a01 = 0, a23 = 0, b01 = 0, b23 = 0;
        float acc2 = 0.f;
        int it = (cnt + 3) >> 2;
        for (int k = 0; k < it; k++) {
            uint2 u = *(const uint2*)&slist[4 * k];       // uniform: 4 indices
            int j0 = u.x & 0xffff, j1 = u.x >> 16;
            int j2 = u.y & 0xffff, j3 = u.y >> 16;
            {
                ulonglong2 vA = wf[j0 * 50 + lane];
                ulonglong2 vB = wf[j0 * 50 + 32 + lane];  // lane>=18: unused junk (in-bounds)
                ADD2(a01, vA.x); ADD2(a23, vA.y); ADD2(b01, vB.x); ADD2(b23, vB.y);
                if (has2) acc2 += sW2[j0 * NOUT + lane];
            }
            {
                ulonglong2 vA = wf[j1 * 50 + lane];
                ulonglong2 vB = wf[j1 * 50 + 32 + lane];
                ADD2(a01, vA.x); ADD2(a23, vA.y); ADD2(b01, vB.x); ADD2(b23, vB.y);
                if (has2) acc2 += sW2[j1 * NOUT + lane];
            }
            {
                ulonglong2 vA = wf[j2 * 50 + lane];
                ulonglong2 vB = wf[j2 * 50 + 32 + lane];
                ADD2(a01, vA.x); ADD2(a23, vA.y); ADD2(b01, vB.x); ADD2(b23, vB.y);
                if (has2) acc2 += sW2[j2 * NOUT + lane];
            }
            {
                ulonglong2 vA = wf[j3 * 50 + lane];
                ulonglong2 vB = wf[j3 * 50 + 32 + lane];
                ADD2(a01, vA.x); ADD2(a23, vA.y); ADD2(b01, vB.x); ADD2(b23, vB.y);
                if (has2) acc2 += sW2[j3 * NOUT + lane];
            }
        }
        float4 gA, gB;
        cvt.u = a01; gA.x = cvt.f.x; gA.y = cvt.f.y;
        cvt.u = a23; gA.z = cvt.f.x; gA.w = cvt.f.y;
        cvt.u = b01; gB.x = cvt.f.x; gB.y = cvt.f.y;
        cvt.u = b23; gB.z = cvt.f.x; gB.w = cvt.f.y;

        // ---- layer-1 state update ----
        float c, r;
        bool sA0, sA1, sA2, sA3, sB0 = false, sB1 = false, sB2 = false, sB3 = false;
        c = gA.x + ffA.x + fA.x; synA.x = aA.x * synA.x + c;
        r = (memA.x > tA.x) ? tA.x : 0.f; memA.x = bA.x * memA.x + synA.x - r; sA0 = memA.x > tA.x;
        c = gA.y + ffA.y + fA.y; synA.y = aA.y * synA.y + c;
        r = (memA.y > tA.y) ? tA.y : 0.f; memA.y = bA.y * memA.y + synA.y - r; sA1 = memA.y > tA.y;
        c = gA.z + ffA.z + fA.z; synA.z = aA.z * synA.z + c;
        r = (memA.z > tA.z) ? tA.z : 0.f; memA.z = bA.z * memA.z + synA.z - r; sA2 = memA.z > tA.z;
        c = gA.w + ffA.w + fA.w; synA.w = aA.w * synA.w + c;
        r = (memA.w > tA.w) ? tA.w : 0.f; memA.w = bA.w * memA.w + synA.w - r; sA3 = memA.w > tA.w;
        if (hasB) {
            c = gB.x + ffB.x + fB.x; synB.x = aB.x * synB.x + c;
            r = (memB.x > tB.x) ? tB.x : 0.f; memB.x = bB.x * memB.x + synB.x - r; sB0 = memB.x > tB.x;
            c = gB.y + ffB.y + fB.y; synB.y = aB.y * synB.y + c;
            r = (memB.y > tB.y) ? tB.y : 0.f; memB.y = bB.y * memB.y + synB.y - r; sB1 = memB.y > tB.y;
            c = gB.z + ffB.z + fB.z; synB.z = aB.z * synB.z + c;
            r = (memB.z > tB.z) ? tB.z : 0.f; memB.z = bB.z * memB.z + synB.z - r; sB2 = memB.z > tB.z;
            c = gB.w + ffB.w + fB.w; synB.w = aB.w * synB.w + c;
            r = (memB.w > tB.w) ? tB.w : 0.f; memB.w = bB.w * memB.w + synB.w - r; sB3 = memB.w > tB.w;
        }

        __syncwarp();   // gather reads done before list rebuild

        // ---- build new spike list (8 ballots) ----
        int nc = 0; unsigned m;
        m = __ballot_sync(0xffffffffu, sA0); if (sA0) slist[nc + __popc(m & lt)] = (unsigned short)(hA);     nc += __popc(m);
        m = __ballot_sync(0xffffffffu, sA1); if (sA1) slist[nc + __popc(m & lt)] = (unsigned short)(hA + 1); nc += __popc(m);
        m = __ballot_sync(0xffffffffu, sA2); if (sA2) slist[nc + __popc(m & lt)] = (unsigned short)(hA + 2); nc += __popc(m);
        m = __ballot_sync(0xffffffffu, sA3); if (sA3) slist[nc + __popc(m & lt)] = (unsigned short)(hA + 3); nc += __popc(m);
        m = __ballot_sync(0xffffffffu, sB0); if (sB0) slist[nc + __popc(m & lt)] = (unsigned short)(hB);     nc += __popc(m);
        m = __ballot_sync(0xffffffffu, sB1); if (sB1) slist[nc + __popc(m & lt)] = (unsigned short)(hB + 1); nc += __popc(m);
        m = __ballot_sync(0xffffffffu, sB2); if (sB2) slist[nc + __popc(m & lt)] = (unsigned short)(hB + 2); nc += __popc(m);
        m = __ballot_sync(0xffffffffu, sB3); if (sB3) slist[nc + __popc(m & lt)] = (unsigned short)(hB + 3); nc += __popc(m);
        if (lane == 0) { int cp = nc; while (cp & 3) slist[cp++] = 200; }
        __syncwarp();   // list visible

        // ---- layer-2 state update for step t-1 (deferred) ----
        if (t > 0 && has2) {
            float cur2 = acc2 + bb2;
            syn2 = a2 * syn2 + cur2;
            float r2 = (mem2 > th2) ? th2 : 0.f;
            mem2 = b2v * mem2 + syn2 - r2;
            rmax = fmaxf(rmax, mem2);
        }

        cnt = nc; ffA = nfA; ffB = nfB;
    }

    // ---- epilogue: layer-2 for step TT-1 from final list ----
    {
        float acc2 = 0.f;
        int it = (cnt + 3) >> 2;
        for (int k = 0; k < it; k++) {
            uint2 u = *(const uint2*)&slist[4 * k];
            int j0 = u.x & 0xffff, j1 = u.x >> 16;
            int j2 = u.y & 0xffff, j3 = u.y >> 16;
            if (has2)
                acc2 += (sW2[j0 * NOUT + lane] + sW2[j1 * NOUT + lane]) +
                        (sW2[j2 * NOUT + lane] + sW2[j3 * NOUT + lane]);
        }
        if (has2) {
            float cur2 = acc2 + bb2;
            syn2 = a2 * syn2 + cur2;
            float r2 = (mem2 > th2) ? th2 : 0.f;
            mem2 = b2v * mem2 + syn2 - r2;
            rmax = fmaxf(rmax, mem2);
        }
    }

    // ---- softmax over 20 outputs ----
    float v = has2 ? rmax : __int_as_float(0xff800000u);
#pragma unroll
    for (int d = 16; d; d >>= 1) v = fmaxf(v, __shfl_xor_sync(0xffffffffu, v, d));
    float e = has2 ? expf(rmax - v) : 0.f;
    float ssum = e;
#pragma unroll
    for (int d = 16; d; d >>= 1) ssum += __shfl_xor_sync(0xffffffffu, ssum, d);
    if (has2) out[b * NOUT + lane] = e / ssum;
}

// ===========================================================================
extern "C" void kernel_launch(void* const* d_in, const int* in_sizes, int n_in,
                              void* d_out, int out_size)
{
    const float* x      = (const float*)d_in[0];
    const float* W1     = (const float*)d_in[1];
    const float* b1     = (const float*)d_in[2];
    const float* Wfb    = (const float*)d_in[3];
    const float* bfb    = (const float*)d_in[4];
    const float* W2     = (const float*)d_in[5];
    const float* b2     = (const float*)d_in[6];
    const float* alpha1 = (const float*)d_in[7];
    const float* beta1  = (const float*)d_in[8];
    const float* thr1   = (const float*)d_in[9];
    const float* alpha2 = (const float*)d_in[10];
    const float* beta2  = (const float*)d_in[11];
    const float* thr2   = (const float*)d_in[12];
    float* out = (float*)d_out;

    cudaFuncSetAttribute(k_ff,  cudaFuncAttributeMaxDynamicSharedMemorySize, P1_SMEM);
    cudaFuncSetAttribute(k_snn, cudaFuncAttributeMaxDynamicSharedMemorySize, P2_SMEM);

    k_compact<<<NROWS / 8, 256>>>(x);
    k_ff<<<dim3(4, P1_GROUPS), 512, P1_SMEM>>>(W1, b1);
    k_snn<<<BB, 32, P2_SMEM>>>(Wfb, bfb, W2, b2,
                               alpha1, beta1, thr1,
                               alpha2, beta2, thr2, out);
}